// round 6
// baseline (speedup 1.0000x reference)
#include <cuda_runtime.h>
#include <math.h>

// ---------------- problem constants ----------------
#define NB 16              // buckets = 2 classes * 8 subgroups
#define NP 512             // points per bucket
#define ND 512             // feature dim
#define N2 (512*512)
#define NPAIR 56           // 2 classes * 28 subgroup pairs
#define NTASK (NPAIR*4)    // 4 potentials per pair

// scratch layout (floats)
constexpr size_t OFF_FEATS   = 0;
constexpr size_t OFF_SQN     = OFF_FEATS + (size_t)NB*N2;
constexpr size_t OFF_DMIN    = OFF_SQN + 8192;
constexpr size_t OFF_DMAX    = OFF_DMIN + 8192;
constexpr size_t OFF_EPS0    = OFF_DMAX + 8192;                    // 56 eps0 (pad 64)
constexpr size_t OFF_CCROSS  = OFF_EPS0 + 64;                      // 56 cross cost matrices
constexpr size_t OFF_CSELF   = OFF_CCROSS + (size_t)NPAIR*N2;      // 16 self cost matrices
constexpr size_t OFF_POT     = OFF_CSELF + (size_t)NB*N2;          // 2 x 224 x 512 potentials
constexpr size_t SCRATCH_TOTAL = OFF_POT + (size_t)2*NTASK*512;

__device__ __align__(16) float g_scratch[SCRATCH_TOTAL];
__device__ int   g_idx[NB*NP];

// triu_indices(8, k=1)
__constant__ int c_pa[28] = {0,0,0,0,0,0,0,1,1,1,1,1,1,2,2,2,2,2,3,3,3,3,4,4,4,5,5,6};
__constant__ int c_pb[28] = {1,2,3,4,5,6,7,2,3,4,5,6,7,3,4,5,6,7,4,5,6,7,5,6,7,6,7,7};
// for each class-local bucket: the 7 (pairIdx*2 + isBslot) entries that use its self matrix
__constant__ int c_selftab[8][7] = {
    {0,2,4,6,8,10,12},
    {1,14,16,18,20,22,24},
    {3,15,26,28,30,32,34},
    {5,17,27,36,38,40,42},
    {7,19,29,37,44,46,48},
    {9,21,31,39,45,50,52},
    {11,23,33,41,47,51,54},
    {13,25,35,43,49,53,55}};

__device__ __forceinline__ float ex2f(float x) {
    float y;
    asm("ex2.approx.ftz.f32 %0, %1;" : "=f"(y) : "f"(x));
    return y;
}

// ---------------- stage 1: stable counting sort ----------------
__global__ void rank_kernel(const int* __restrict__ labels, const int* __restrict__ subgroups) {
    __shared__ int s[256];
    __shared__ int sbase;
    int key = blockIdx.x;
    if (threadIdx.x == 0) sbase = 0;
    __syncthreads();
    for (int c0 = 0; c0 < 8192; c0 += 256) {
        int i = c0 + threadIdx.x;
        int k = labels[i] * 8 + subgroups[i];
        int f = (k == key) ? 1 : 0;
        s[threadIdx.x] = f;
        __syncthreads();
        #pragma unroll
        for (int off = 1; off < 256; off <<= 1) {
            int v = (threadIdx.x >= (unsigned)off) ? s[threadIdx.x - off] : 0;
            __syncthreads();
            s[threadIdx.x] += v;
            __syncthreads();
        }
        if (f) g_idx[key * NP + sbase + s[threadIdx.x] - 1] = i;
        __syncthreads();
        if (threadIdx.x == 0) sbase += s[255];
        __syncthreads();
    }
}

// ---------------- stage 2: gather + norms + min/max + eps0 ----------------
__global__ void gather_kernel(const float* __restrict__ feats) {
    size_t total = (size_t)NB * N2;
    for (size_t idx = (size_t)blockIdx.x * blockDim.x + threadIdx.x; idx < total;
         idx += (size_t)gridDim.x * blockDim.x) {
        int d   = (int)(idx & 511);
        int r   = (int)((idx >> 9) & 511);
        int bkt = (int)(idx >> 18);
        g_scratch[OFF_FEATS + idx] = feats[(size_t)g_idx[bkt * NP + r] * ND + d];
    }
}

__global__ void sqn_kernel() {
    int wid = threadIdx.x >> 5, lane = threadIdx.x & 31;
    int row = blockIdx.x * 8 + wid;
    const float* f = g_scratch + OFF_FEATS + (size_t)row * ND;
    float s = 0.f;
    #pragma unroll
    for (int q = 0; q < 16; q++) { float v = f[lane + q * 32]; s = fmaf(v, v, s); }
    #pragma unroll
    for (int off = 16; off; off >>= 1) s += __shfl_xor_sync(0xffffffffu, s, off);
    if (lane == 0) g_scratch[OFF_SQN + row] = s;
}

__global__ void minmax_kernel() {
    int idx = blockIdx.x * 256 + threadIdx.x;
    int b = idx >> 9, d = idx & 511;
    const float* base = g_scratch + OFF_FEATS + (size_t)b * N2 + d;
    float mn = base[0], mx = base[0];
    for (int p = 1; p < NP; p++) {
        float v = base[(size_t)p * ND];
        mn = fminf(mn, v); mx = fmaxf(mx, v);
    }
    g_scratch[OFF_DMIN + idx] = mn;
    g_scratch[OFF_DMAX + idx] = mx;
}

__global__ void eps0_kernel() {
    int w = blockIdx.x * 8 + (threadIdx.x >> 5);
    int lane = threadIdx.x & 31;
    if (w >= NPAIR) return;
    int kk = w % 28, cls = w / 28;
    int a = cls * 8 + c_pa[kk], b = cls * 8 + c_pb[kk];
    const float* dmin = g_scratch + OFF_DMIN;
    const float* dmax = g_scratch + OFF_DMAX;
    float s = 0.f;
    #pragma unroll
    for (int q = 0; q < 16; q++) {
        int d = lane + q * 32;
        float mx = fmaxf(dmax[a * ND + d], dmax[b * ND + d]);
        float mn = fminf(dmin[a * ND + d], dmin[b * ND + d]);
        float rr = mx - mn;
        s = fmaf(rr, rr, s);
    }
    #pragma unroll
    for (int off = 16; off; off >>= 1) s += __shfl_xor_sync(0xffffffffu, s, off);
    if (lane == 0) {
        float diam = sqrtf(s);
        g_scratch[OFF_EPS0 + w] = diam * diam;
    }
}

// ---------------- stage 3: cost matrices ----------------
__global__ void gemm_kernel() {
    int job = blockIdx.y;
    int ta, tb; size_t outoff;
    if (job < NPAIR) {
        int cls = job / 28, k = job % 28;
        ta = cls * 8 + c_pa[k]; tb = cls * 8 + c_pb[k];
        outoff = OFF_CCROSS + (size_t)job * N2;
    } else {
        int sb = job - NPAIR;
        ta = tb = sb;
        outoff = OFF_CSELF + (size_t)sb * N2;
    }
    int tm = (blockIdx.x >> 3) << 6;
    int tn = (blockIdx.x & 7) << 6;
    const float* A = g_scratch + OFF_FEATS + (size_t)ta * N2;
    const float* B = g_scratch + OFF_FEATS + (size_t)tb * N2;

    __shared__ float As[32][68];
    __shared__ float Bs[32][68];

    int tid = threadIdx.x;
    int tx = tid & 15, ty = tid >> 4;
    int r  = tid >> 3;
    int c4 = (tid & 7) << 2;

    float acc[4][4];
    #pragma unroll
    for (int i = 0; i < 4; i++)
        #pragma unroll
        for (int j = 0; j < 4; j++) acc[i][j] = 0.f;

    for (int k0 = 0; k0 < ND; k0 += 32) {
        float4 a0 = *(const float4*)(A + (size_t)(tm + r)      * ND + k0 + c4);
        float4 a1 = *(const float4*)(A + (size_t)(tm + r + 32) * ND + k0 + c4);
        float4 b0 = *(const float4*)(B + (size_t)(tn + r)      * ND + k0 + c4);
        float4 b1 = *(const float4*)(B + (size_t)(tn + r + 32) * ND + k0 + c4);
        As[c4+0][r] = a0.x; As[c4+1][r] = a0.y; As[c4+2][r] = a0.z; As[c4+3][r] = a0.w;
        As[c4+0][r+32] = a1.x; As[c4+1][r+32] = a1.y; As[c4+2][r+32] = a1.z; As[c4+3][r+32] = a1.w;
        Bs[c4+0][r] = b0.x; Bs[c4+1][r] = b0.y; Bs[c4+2][r] = b0.z; Bs[c4+3][r] = b0.w;
        Bs[c4+0][r+32] = b1.x; Bs[c4+1][r+32] = b1.y; Bs[c4+2][r+32] = b1.z; Bs[c4+3][r+32] = b1.w;
        __syncthreads();
        #pragma unroll
        for (int kk = 0; kk < 32; kk++) {
            float4 av = *(const float4*)&As[kk][ty << 2];
            float4 bv = *(const float4*)&Bs[kk][tx << 2];
            float a[4] = {av.x, av.y, av.z, av.w};
            float b[4] = {bv.x, bv.y, bv.z, bv.w};
            #pragma unroll
            for (int i = 0; i < 4; i++)
                #pragma unroll
                for (int j = 0; j < 4; j++) acc[i][j] = fmaf(a[i], b[j], acc[i][j]);
        }
        __syncthreads();
    }

    const float* sa = g_scratch + OFF_SQN + (size_t)ta * NP;
    const float* sb = g_scratch + OFF_SQN + (size_t)tb * NP;
    float* Co = g_scratch + outoff;
    #pragma unroll
    for (int i = 0; i < 4; i++) {
        int row = tm + (ty << 2) + i;
        float h = 0.5f * sa[row];
        #pragma unroll
        for (int j = 0; j < 4; j++) {
            int col = tn + (tx << 2) + j;
            Co[(size_t)row * NP + col] = fmaxf(h + 0.5f * sb[col] - acc[i][j], 0.0f);
        }
    }
}

// ---------------- stage 4: one fused step kernel ----------------
// grid (64, 128), block 256.
//   jobs 0..55   : cross row softmin (f_ba update), 8 rows/block, x=0..63
//   jobs 56..111 : cross col softmin (g_ab update), 16 cols/block, x=0..31 (x>=32 idle)
//   jobs 112..127: self softmin batched over 7 (pair,slot) tasks, 8 rows/block
// mode 0: init (eps=eps0, g=0, no avg); 1: step (avg); 2: final (eps=1e-8, no avg)
#define SLAB_STRIDE 516

__global__ void __launch_bounds__(256) step_kernel(float sfac, int mode, int bOld, int bNew) {
    __shared__ float pool[16 * SLAB_STRIDE];   // col: transposed slab; self: 7x512 gsc; row: 512 gsc
    __shared__ float gcol[512];                // col: scaled f potential
    __shared__ float sh_eps[8], sh_nk2[8];

    int job = blockIdx.y;
    int tid = threadIdx.x;
    int lane = tid & 31, warp = tid >> 5;

    const float* potOld = g_scratch + OFF_POT + (size_t)bOld * NTASK * 512;
    float*       potNew = g_scratch + OFF_POT + (size_t)bNew * NTASK * 512;

    if (job < 112) {
        int colj = (job >= 56);
        int p = colj ? job - 56 : job;
        if (colj && blockIdx.x >= 32) return;

        if (tid == 0) {
            float e0 = g_scratch[OFF_EPS0 + p];
            float eps = (mode == 0) ? e0 : (mode == 2) ? 1e-8f : fmaxf(e0 * sfac, 1e-8f);
            sh_eps[0] = eps;
            sh_nk2[0] = -1.4426950408889634f / eps;
        }
        __syncthreads();
        float eps = sh_eps[0], nk2 = sh_nk2[0];

        int gslot = colj ? 0 : 1;   // col uses f (slot0) -> writes g (slot1); row vice versa
        int oslot = colj ? 1 : 0;
        const float* pin  = potOld + (size_t)(p * 4 + gslot) * 512;
        const float* pavg = potOld + (size_t)(p * 4 + oslot) * 512;
        float*       pout = potNew + (size_t)(p * 4 + oslot) * 512;
        float* gbuf = colj ? gcol : pool;
        for (int i = tid; i < 512; i += 256)
            gbuf[i] = (mode == 0) ? 0.f : pin[i] * (-nk2);

        const float* C = g_scratch + OFF_CCROSS + (size_t)p * N2;

        if (!colj) {
            __syncthreads();
            int row = blockIdx.x * 8 + warp;
            const float4* Crow = (const float4*)(C + (size_t)row * 512);
            const float4* G = (const float4*)gbuf;
            float v[16];
            float vmax = -3.4e38f;
            #pragma unroll
            for (int q = 0; q < 4; q++) {
                float4 c = Crow[lane + q * 32];
                float4 g = G[lane + q * 32];
                v[q*4+0] = fmaf(c.x, nk2, g.x);
                v[q*4+1] = fmaf(c.y, nk2, g.y);
                v[q*4+2] = fmaf(c.z, nk2, g.z);
                v[q*4+3] = fmaf(c.w, nk2, g.w);
                vmax = fmaxf(vmax, fmaxf(fmaxf(v[q*4+0], v[q*4+1]), fmaxf(v[q*4+2], v[q*4+3])));
            }
            #pragma unroll
            for (int off = 16; off; off >>= 1)
                vmax = fmaxf(vmax, __shfl_xor_sync(0xffffffffu, vmax, off));
            float s = 0.f;
            #pragma unroll
            for (int q = 0; q < 16; q++) s += ex2f(v[q] - vmax);
            #pragma unroll
            for (int off = 16; off; off >>= 1)
                s += __shfl_xor_sync(0xffffffffu, s, off);
            if (lane == 0) {
                float res = -eps * 0.6931471805599453f * (vmax + __log2f(s) - 9.0f);
                pout[row] = (mode == 1) ? 0.5f * (pavg[row] + res) : res;
            }
        } else {
            // stage 16-column slab, transposed, via coalesced tile loads
            int tx = tid & 15, ty = tid >> 4;
            int c0 = blockIdx.x * 16;
            #pragma unroll 4
            for (int r0 = 0; r0 < 512; r0 += 16)
                pool[tx * SLAB_STRIDE + r0 + ty] = C[(size_t)(r0 + ty) * 512 + c0 + tx];
            __syncthreads();
            #pragma unroll
            for (int cc = 0; cc < 2; cc++) {
                int cl = warp * 2 + cc;
                const float4* Crow = (const float4*)(pool + cl * SLAB_STRIDE);
                const float4* G = (const float4*)gcol;
                float v[16];
                float vmax = -3.4e38f;
                #pragma unroll
                for (int q = 0; q < 4; q++) {
                    float4 c = Crow[lane + q * 32];
                    float4 g = G[lane + q * 32];
                    v[q*4+0] = fmaf(c.x, nk2, g.x);
                    v[q*4+1] = fmaf(c.y, nk2, g.y);
                    v[q*4+2] = fmaf(c.z, nk2, g.z);
                    v[q*4+3] = fmaf(c.w, nk2, g.w);
                    vmax = fmaxf(vmax, fmaxf(fmaxf(v[q*4+0], v[q*4+1]), fmaxf(v[q*4+2], v[q*4+3])));
                }
                #pragma unroll
                for (int off = 16; off; off >>= 1)
                    vmax = fmaxf(vmax, __shfl_xor_sync(0xffffffffu, vmax, off));
                float s = 0.f;
                #pragma unroll
                for (int q = 0; q < 16; q++) s += ex2f(v[q] - vmax);
                #pragma unroll
                for (int off = 16; off; off >>= 1)
                    s += __shfl_xor_sync(0xffffffffu, s, off);
                if (lane == 0) {
                    int col = c0 + cl;
                    float res = -eps * 0.6931471805599453f * (vmax + __log2f(s) - 9.0f);
                    pout[col] = (mode == 1) ? 0.5f * (pavg[col] + res) : res;
                }
            }
        }
    } else {
        // ---- self: one C matrix serves 7 (pair, slot) tasks ----
        int sb = job - 112;
        int cls = sb >> 3, bkt = sb & 7;
        if (tid < 7) {
            int e = c_selftab[bkt][tid];
            int p = cls * 28 + (e >> 1);
            float e0 = g_scratch[OFF_EPS0 + p];
            float eps = (mode == 0) ? e0 : (mode == 2) ? 1e-8f : fmaxf(e0 * sfac, 1e-8f);
            sh_eps[tid] = eps;
            sh_nk2[tid] = -1.4426950408889634f / eps;
        }
        __syncthreads();
        for (int i = tid; i < 7 * 512; i += 256) {
            int t = i >> 9, j = i & 511;
            int e = c_selftab[bkt][t];
            int p = cls * 28 + (e >> 1);
            int slot = 2 + (e & 1);
            pool[i] = (mode == 0) ? 0.f
                                  : potOld[(size_t)(p * 4 + slot) * 512 + j] * (-sh_nk2[t]);
        }
        __syncthreads();

        const float* C = g_scratch + OFF_CSELF + (size_t)(cls * 8 + bkt) * N2;
        int row = blockIdx.x * 8 + warp;
        const float4* Crow = (const float4*)(C + (size_t)row * 512);
        float4 cv[4];
        #pragma unroll
        for (int q = 0; q < 4; q++) cv[q] = Crow[lane + q * 32];

        #pragma unroll
        for (int t = 0; t < 7; t++) {
            float nk2 = sh_nk2[t], eps = sh_eps[t];
            const float4* G = (const float4*)(pool + t * 512);
            float v[16];
            float vmax = -3.4e38f;
            #pragma unroll
            for (int q = 0; q < 4; q++) {
                float4 g = G[lane + q * 32];
                v[q*4+0] = fmaf(cv[q].x, nk2, g.x);
                v[q*4+1] = fmaf(cv[q].y, nk2, g.y);
                v[q*4+2] = fmaf(cv[q].z, nk2, g.z);
                v[q*4+3] = fmaf(cv[q].w, nk2, g.w);
                vmax = fmaxf(vmax, fmaxf(fmaxf(v[q*4+0], v[q*4+1]), fmaxf(v[q*4+2], v[q*4+3])));
            }
            #pragma unroll
            for (int off = 16; off; off >>= 1)
                vmax = fmaxf(vmax, __shfl_xor_sync(0xffffffffu, vmax, off));
            float s = 0.f;
            #pragma unroll
            for (int q = 0; q < 16; q++) s += ex2f(v[q] - vmax);
            #pragma unroll
            for (int off = 16; off; off >>= 1)
                s += __shfl_xor_sync(0xffffffffu, s, off);
            if (lane == 0) {
                int e = c_selftab[bkt][t];
                int p = cls * 28 + (e >> 1);
                int slot = 2 + (e & 1);
                size_t idx = (size_t)(p * 4 + slot) * 512 + row;
                float res = -eps * 0.6931471805599453f * (vmax + __log2f(s) - 9.0f);
                potNew[idx] = (mode == 1) ? 0.5f * (potOld[idx] + res) : res;
            }
        }
    }
}

// ---------------- stage 5: final reduction ----------------
__global__ void reduce_kernel(int bFin, float* __restrict__ out) {
    __shared__ float sh[1024];
    const float* pot = g_scratch + OFF_POT + (size_t)bFin * NTASK * 512;
    float s = 0.f;
    for (int i = threadIdx.x; i < NTASK * 512; i += 1024) {
        int slot = (i >> 9) & 3;
        float v = pot[i];
        s += (slot < 2) ? v : -v;
    }
    sh[threadIdx.x] = s;
    __syncthreads();
    for (int off = 512; off; off >>= 1) {
        if (threadIdx.x < off) sh[threadIdx.x] += sh[threadIdx.x + off];
        __syncthreads();
    }
    if (threadIdx.x == 0) out[0] = sh[0] / (512.0f * 56.0f);
}

// ---------------- launch ----------------
extern "C" void kernel_launch(void* const* d_in, const int* in_sizes, int n_in,
                              void* d_out, int out_size) {
    const float* features  = (const float*)d_in[0];
    const int*   labels    = (const int*)d_in[1];
    const int*   subgroups = (const int*)d_in[2];
    float* out = (float*)d_out;

    rank_kernel<<<16, 256>>>(labels, subgroups);
    gather_kernel<<<4096, 256>>>(features);
    sqn_kernel<<<1024, 256>>>();
    minmax_kernel<<<32, 256>>>();
    eps0_kernel<<<7, 256>>>();
    gemm_kernel<<<dim3(64, 72), 256>>>();

    dim3 sgrid(64, 128);
    // init: writes buffer 0
    step_kernel<<<sgrid, 256>>>(0.f, 0, 1, 0);
    // 140 scan steps: step t reads t%2, writes 1-t%2 (eps factor 0.81^t, host-computed)
    for (int t = 0; t < 140; t++) {
        float sfac = (float)pow(0.81, (double)t);
        int bOld = t & 1;
        step_kernel<<<sgrid, 256>>>(sfac, 1, bOld, 1 - bOld);
    }
    // after t=139 result sits in buffer 0; final extrapolation writes buffer 1
    step_kernel<<<sgrid, 256>>>(0.f, 2, 0, 1);
    reduce_kernel<<<1, 1024>>>(1, out);
}